// round 1
// baseline (speedup 1.0000x reference)
#include <cuda_runtime.h>
#include <math.h>

#define BB   4
#define NN   16384
#define CIN  128
#define COUT 256
#define HH   256
#define WW   256
#define NP   65536      // N0 = H*W points
#define HD   128
#define WD   128
#define HC   64
#define WC   64
#define NS   4096       // HC*WC
#define EPSV 1e-6f

// ---------------- scratch (device globals: no allocation allowed) ----------------
__device__ float  g_ssum[(size_t)BB*HH*WW*CIN];   // token2map sum      (128MB)
__device__ float  g_cnt [(size_t)BB*HH*WW];       // token2map count
__device__ float  g_y   [(size_t)BB*HD*WD*COUT];  // conv output        (64MB)
__device__ float  g_num [(size_t)BB*NN*COUT];     // map2token num -> tok (64MB)
__device__ float  g_den [(size_t)BB*NN];
__device__ float  g_tokn[(size_t)BB*NN*COUT];     // BN-normalized tokens (64MB)
__device__ float  g_wexp[(size_t)BB*NN];          // exp(conf)
__device__ double g_bnsum[COUT];
__device__ double g_bnsq [COUT];
__device__ float  g_scale[COUT];
__device__ float  g_shift[COUT];
__device__ float  g_cnum[(size_t)BB*NS*COUT];     // cluster num (16MB)
__device__ float  g_cden[(size_t)BB*NS];
__device__ float  g_wpt [(size_t)BB*NP];          // per-point weight, reused for agg_weight_down
__device__ unsigned g_maxw[BB];
__device__ float  g_wT  [CIN*COUT];               // skip_w transposed [k][n]

// ---------------- helpers ----------------
__device__ __forceinline__ void red_add4(float* p, float4 v) {
    asm volatile("red.global.add.v4.f32 [%0], {%1,%2,%3,%4};"
                 :: "l"(__cvta_generic_to_global(p)),
                    "f"(v.x), "f"(v.y), "f"(v.z), "f"(v.w) : "memory");
}

__device__ __forceinline__ int grid_cell(float lx, float ly, int Hg, int Wg) {
    lx = fminf(fmaxf(lx, -1.f), 1.f);
    ly = fminf(fmaxf(ly, -1.f), 1.f);
    int px = min(max(__float2int_rn(0.5f*(lx+1.f)*(float)Wg - 0.5f), 0), Wg-1);
    int py = min(max(__float2int_rn(0.5f*(ly+1.f)*(float)Hg - 0.5f), 0), Hg-1);
    return py*Wg + px;
}

// ---------------- kernels ----------------
__global__ void k_zero() {
    size_t t = (size_t)blockIdx.x*blockDim.x + threadIdx.x;
    size_t stride = (size_t)gridDim.x*blockDim.x;
    float4 z = make_float4(0.f,0.f,0.f,0.f);
    for (size_t i=t; i < (size_t)BB*HH*WW*CIN/4; i+=stride) ((float4*)g_ssum)[i]=z;
    for (size_t i=t; i < (size_t)BB*HH*WW/4;     i+=stride) ((float4*)g_cnt )[i]=z;
    for (size_t i=t; i < (size_t)BB*NN*COUT/4;   i+=stride) ((float4*)g_num )[i]=z;
    for (size_t i=t; i < (size_t)BB*NN/4;        i+=stride) ((float4*)g_den )[i]=z;
    for (size_t i=t; i < (size_t)BB*NS*COUT/4;   i+=stride) ((float4*)g_cnum)[i]=z;
    for (size_t i=t; i < (size_t)BB*NS/4;        i+=stride) ((float4*)g_cden)[i]=z;
    if (t < COUT) { g_bnsum[t]=0.0; g_bnsq[t]=0.0; }
    if (t < BB)   g_maxw[t]=0u;
}

// scatter token features to H x W map (sum + count)
__global__ void k_token2map(const float* __restrict__ x, const float* __restrict__ loc,
                            const int* __restrict__ idx_agg) {
    int p    = blockIdx.x*8 + (threadIdx.x>>5);
    int lane = threadIdx.x & 31;
    int b    = p >> 16;                               // NP = 2^16
    float lx = loc[2*p], ly = loc[2*p+1];
    int cell = grid_cell(lx, ly, HH, WW);
    int i    = idx_agg[p];
    const float4* src = (const float4*)(x + ((size_t)b*NN + i)*CIN);
    float* dst = g_ssum + ((size_t)b*HH*WW + cell)*CIN;
    float4 v = src[lane];
    red_add4(dst + lane*4, v);
    if (!lane) atomicAdd(&g_cnt[(size_t)b*HH*WW + cell], 1.0f);
}

__global__ void k_transpose(const float* __restrict__ w) { // w[COUT][CIN] -> g_wT[CIN][COUT]
    int t = blockIdx.x*blockDim.x + threadIdx.x;          // 32768
    g_wT[t] = w[(t % COUT)*CIN + (t / COUT)];
}

// 3x3 stride-2 conv as implicit SGEMM: M=pixels (tiled 8x8), N=cout, K=9*CIN
__global__ void __launch_bounds__(256) k_conv(const float* __restrict__ cw,
                                              const float* __restrict__ cb) {
    __shared__ __align__(16) float As[16][68];
    __shared__ __align__(16) float Bs[16][64];
    int b  = blockIdx.z >> 2, nt = blockIdx.z & 3;
    int oy0 = blockIdx.y*8, ox0 = blockIdx.x*8;
    int n0 = nt*64;
    int tid = threadIdx.x;
    int tx = tid & 15, ty = tid >> 4;
    int m_l = tid >> 2, kq = (tid & 3)*4;      // A load: pixel m_l, 4 cin at kq
    int kb  = tid >> 4, nb = (tid & 15)*4;     // B load: k row kb, 4 cout at nb
    int oy = oy0 + (m_l >> 3), ox = ox0 + (m_l & 7);
    float acc[4][4] = {};
    for (int tap = 0; tap < 9; tap++) {
        int ky = tap / 3, kx = tap - 3*ky;
        int iy = 2*oy - 1 + ky, ix = 2*ox - 1 + kx;
        bool valid = (iy >= 0 && iy < HH && ix >= 0 && ix < WW);
        const float* arow = g_ssum + ((size_t)b*HH*WW + (size_t)iy*WW + ix)*CIN;
        float rcp = valid ? 1.f/(g_cnt[(size_t)b*HH*WW + iy*WW + ix] + EPSV) : 0.f;
        const float* brow = cw + (size_t)tap*CIN*COUT;
        for (int cc = 0; cc < 8; cc++) {
            float4 va = make_float4(0.f,0.f,0.f,0.f);
            if (valid) va = *(const float4*)(arow + cc*16 + kq);
            va.x *= rcp; va.y *= rcp; va.z *= rcp; va.w *= rcp;
            __syncthreads();
            As[kq+0][m_l]=va.x; As[kq+1][m_l]=va.y; As[kq+2][m_l]=va.z; As[kq+3][m_l]=va.w;
            *(float4*)&Bs[kb][nb] = *(const float4*)(brow + (size_t)(cc*16+kb)*COUT + n0 + nb);
            __syncthreads();
            #pragma unroll
            for (int k = 0; k < 16; k++) {
                float4 a  = *(float4*)&As[k][ty*4];
                float4 bv = *(float4*)&Bs[k][tx*4];
                acc[0][0]+=a.x*bv.x; acc[0][1]+=a.x*bv.y; acc[0][2]+=a.x*bv.z; acc[0][3]+=a.x*bv.w;
                acc[1][0]+=a.y*bv.x; acc[1][1]+=a.y*bv.y; acc[1][2]+=a.y*bv.z; acc[1][3]+=a.y*bv.w;
                acc[2][0]+=a.z*bv.x; acc[2][1]+=a.z*bv.y; acc[2][2]+=a.z*bv.z; acc[2][3]+=a.z*bv.w;
                acc[3][0]+=a.w*bv.x; acc[3][1]+=a.w*bv.y; acc[3][2]+=a.w*bv.z; acc[3][3]+=a.w*bv.w;
            }
        }
    }
    float4 bias = *(const float4*)(cb + n0 + tx*4);
    #pragma unroll
    for (int i2 = 0; i2 < 4; i2++) {
        int m = ty*4 + i2;
        int oyE = oy0 + (m >> 3), oxE = ox0 + (m & 7);
        float* orow = g_y + (((size_t)b*HD + oyE)*WD + oxE)*COUT + n0 + tx*4;
        float4 o = make_float4(acc[i2][0]+bias.x, acc[i2][1]+bias.y,
                               acc[i2][2]+bias.z, acc[i2][3]+bias.w);
        *(float4*)orow = o;
    }
}

// bilinear gather from conv map at orig points, weighted scatter to tokens
__global__ void k_map2token(const float* __restrict__ loc, const int* __restrict__ idx_agg,
                            const float* __restrict__ aggw) {
    int p    = blockIdx.x*8 + (threadIdx.x>>5);
    int lane = threadIdx.x & 31;
    int b    = p >> 16;
    float lx = fminf(fmaxf(loc[2*p],   -1.f), 1.f);
    float ly = fminf(fmaxf(loc[2*p+1], -1.f), 1.f);
    float fx = fminf(fmaxf(0.5f*(lx+1.f)*(float)WD - 0.5f, 0.f), (float)(WD-1));
    float fy = fminf(fmaxf(0.5f*(ly+1.f)*(float)HD - 0.5f, 0.f), (float)(HD-1));
    float x0f = floorf(fx), y0f = floorf(fy);
    float wx = fx - x0f, wy = fy - y0f;
    int x0 = (int)x0f, y0 = (int)y0f;
    int x1 = min(x0+1, WD-1), y1 = min(y0+1, HD-1);
    const float* base = g_y + (size_t)b*HD*WD*COUT;
    const float4* r00 = (const float4*)(base + (size_t)(y0*WD+x0)*COUT);
    const float4* r01 = (const float4*)(base + (size_t)(y0*WD+x1)*COUT);
    const float4* r10 = (const float4*)(base + (size_t)(y1*WD+x0)*COUT);
    const float4* r11 = (const float4*)(base + (size_t)(y1*WD+x1)*COUT);
    float w00=(1.f-wx)*(1.f-wy), w01=wx*(1.f-wy), w10=(1.f-wx)*wy, w11=wx*wy;
    float wpt = aggw[p];
    int i = idx_agg[p];
    float* dst = g_num + ((size_t)b*NN + i)*COUT;
    #pragma unroll
    for (int q = 0; q < 2; q++) {
        int c4 = q*32 + lane;
        float4 a = r00[c4], bq = r01[c4], c = r10[c4], d = r11[c4];
        float4 f;
        f.x = (w00*a.x + w01*bq.x + w10*c.x + w11*d.x)*wpt;
        f.y = (w00*a.y + w01*bq.y + w10*c.y + w11*d.y)*wpt;
        f.z = (w00*a.z + w01*bq.z + w10*c.z + w11*d.z)*wpt;
        f.w = (w00*a.w + w01*bq.w + w10*c.w + w11*d.w)*wpt;
        red_add4(dst + c4*4, f);
    }
    if (!lane) atomicAdd(&g_den[(size_t)b*NN + i], wpt);
}

// skip GEMM (x @ skip_w^T) fused with tok = num/(den+eps) + skip  -> overwrite g_num
__global__ void __launch_bounds__(256) k_skip(const float* __restrict__ x) {
    __shared__ __align__(16) float As[16][68];
    __shared__ __align__(16) float Bs[16][64];
    int m0 = blockIdx.x*64, n0 = blockIdx.y*64;
    int tid = threadIdx.x;
    int tx = tid & 15, ty = tid >> 4;
    int m_l = tid >> 2, kq = (tid & 3)*4;
    int kb  = tid >> 4, nb = (tid & 15)*4;
    float acc[4][4] = {};
    const float* arow = x + (size_t)(m0 + m_l)*CIN;
    for (int cc = 0; cc < 8; cc++) {
        float4 va = *(const float4*)(arow + cc*16 + kq);
        __syncthreads();
        As[kq+0][m_l]=va.x; As[kq+1][m_l]=va.y; As[kq+2][m_l]=va.z; As[kq+3][m_l]=va.w;
        *(float4*)&Bs[kb][nb] = *(const float4*)(g_wT + (size_t)(cc*16+kb)*COUT + n0 + nb);
        __syncthreads();
        #pragma unroll
        for (int k = 0; k < 16; k++) {
            float4 a  = *(float4*)&As[k][ty*4];
            float4 bv = *(float4*)&Bs[k][tx*4];
            acc[0][0]+=a.x*bv.x; acc[0][1]+=a.x*bv.y; acc[0][2]+=a.x*bv.z; acc[0][3]+=a.x*bv.w;
            acc[1][0]+=a.y*bv.x; acc[1][1]+=a.y*bv.y; acc[1][2]+=a.y*bv.z; acc[1][3]+=a.y*bv.w;
            acc[2][0]+=a.z*bv.x; acc[2][1]+=a.z*bv.y; acc[2][2]+=a.z*bv.z; acc[2][3]+=a.z*bv.w;
            acc[3][0]+=a.w*bv.x; acc[3][1]+=a.w*bv.y; acc[3][2]+=a.w*bv.z; acc[3][3]+=a.w*bv.w;
        }
    }
    #pragma unroll
    for (int i2 = 0; i2 < 4; i2++) {
        int row = m0 + ty*4 + i2;
        float rcp = 1.f/(g_den[row] + EPSV);
        float* orow = g_num + (size_t)row*COUT + n0 + tx*4;
        float4 nv = *(float4*)orow;
        float4 o = make_float4(acc[i2][0] + nv.x*rcp, acc[i2][1] + nv.y*rcp,
                               acc[i2][2] + nv.z*rcp, acc[i2][3] + nv.w*rcp);
        *(float4*)orow = o;
    }
}

__global__ void k_bnstats() {
    int c  = threadIdx.x;                 // channel
    int r0 = blockIdx.x*256;
    double s = 0.0, s2 = 0.0;
    for (int r = 0; r < 256; r++) {
        float v = g_num[(size_t)(r0 + r)*COUT + c];
        s += v; s2 += (double)v*v;
    }
    atomicAdd(&g_bnsum[c], s);
    atomicAdd(&g_bnsq[c],  s2);
}

__global__ void k_bnfinal(const float* __restrict__ gam, const float* __restrict__ bet) {
    int c = threadIdx.x;
    double m  = (double)BB*NN;
    double mu = g_bnsum[c]/m;
    double var = g_bnsq[c]/m - mu*mu;
    float sc = gam[c] * (float)(1.0/sqrt(var + 1e-5));
    g_scale[c] = sc;
    g_shift[c] = bet[c] - (float)mu*sc;
}

// apply BN, compute conf + exp(conf), write tokn, x_out=relu(tokn), conf
__global__ void k_bnconf(const float* __restrict__ cw, const float* __restrict__ cbv,
                         float* __restrict__ out_xout, float* __restrict__ out_conf) {
    int row  = blockIdx.x*8 + (threadIdx.x>>5);
    int lane = threadIdx.x & 31;
    const float4* t  = (const float4*)(g_num  + (size_t)row*COUT);
    float4* tn       = (float4*)(g_tokn + (size_t)row*COUT);
    float4* xo       = (float4*)(out_xout + (size_t)row*COUT);
    float dot = 0.f;
    #pragma unroll
    for (int q = 0; q < 2; q++) {
        int c4 = q*32 + lane;
        float4 v  = t[c4];
        float4 sc = ((const float4*)g_scale)[c4];
        float4 sh = ((const float4*)g_shift)[c4];
        float4 w  = ((const float4*)cw)[c4];
        float4 r = make_float4(v.x*sc.x+sh.x, v.y*sc.y+sh.y, v.z*sc.z+sh.z, v.w*sc.w+sh.w);
        dot += r.x*w.x + r.y*w.y + r.z*w.z + r.w*w.w;
        tn[c4] = r;
        xo[c4] = make_float4(fmaxf(r.x,0.f), fmaxf(r.y,0.f), fmaxf(r.z,0.f), fmaxf(r.w,0.f));
    }
    #pragma unroll
    for (int o = 16; o; o >>= 1) dot += __shfl_xor_sync(0xffffffffu, dot, o);
    if (!lane) {
        float cf = dot + cbv[0];
        out_conf[row] = cf;
        g_wexp[row]   = expf(cf);
    }
}

// weighted scatter of tokn into 64x64 cells; also emit idx_agg_down + per-point wpt
__global__ void k_cluster(const float* __restrict__ loc, const int* __restrict__ idx_agg,
                          float* __restrict__ out_idx) {
    int p    = blockIdx.x*8 + (threadIdx.x>>5);
    int lane = threadIdx.x & 31;
    int b    = p >> 16;
    int cell = grid_cell(loc[2*p], loc[2*p+1], HC, WC);
    int i    = idx_agg[p];
    float w  = g_wexp[(size_t)b*NN + i];
    const float4* src = (const float4*)(g_tokn + ((size_t)b*NN + i)*COUT);
    float* dst = g_cnum + ((size_t)b*NS + cell)*COUT;
    #pragma unroll
    for (int q = 0; q < 2; q++) {
        int c4 = q*32 + lane;
        float4 v = src[c4];
        red_add4(dst + c4*4, make_float4(v.x*w, v.y*w, v.z*w, v.w*w));
    }
    if (!lane) {
        atomicAdd(&g_cden[(size_t)b*NS + cell], w);
        g_wpt[p]   = w;
        out_idx[p] = (float)cell;
    }
}

__global__ void k_xdown(float* __restrict__ out_xd) {
    int row  = blockIdx.x*8 + (threadIdx.x>>5);       // BB*NS rows
    int lane = threadIdx.x & 31;
    float rcp = 1.f/(g_cden[row] + EPSV);
    const float4* src = (const float4*)(g_cnum + (size_t)row*COUT);
    float4* dst = (float4*)(out_xd + (size_t)row*COUT);
    #pragma unroll
    for (int q = 0; q < 2; q++) {
        int c4 = q*32 + lane;
        float4 v = src[c4];
        dst[c4] = make_float4(fmaxf(v.x*rcp,0.f), fmaxf(v.y*rcp,0.f),
                              fmaxf(v.z*rcp,0.f), fmaxf(v.w*rcp,0.f));
    }
}

__global__ void k_aggmax(const float* __restrict__ loc, const float* __restrict__ aggw) {
    __shared__ float sm[256];
    int p = blockIdx.x*256 + threadIdx.x;
    int b = p >> 16;
    int cell = grid_cell(loc[2*p], loc[2*p+1], HC, WC);
    float aw = aggw[p] * g_wpt[p] / (g_cden[(size_t)b*NS + cell] + EPSV);
    g_wpt[p] = aw;
    sm[threadIdx.x] = aw;
    __syncthreads();
    for (int s = 128; s; s >>= 1) {
        if (threadIdx.x < s) sm[threadIdx.x] = fmaxf(sm[threadIdx.x], sm[threadIdx.x+s]);
        __syncthreads();
    }
    if (!threadIdx.x) atomicMax(&g_maxw[b], __float_as_uint(sm[0]));   // values >= 0
}

__global__ void k_aggnorm(float* __restrict__ out_aw) {
    int p = blockIdx.x*256 + threadIdx.x;
    int b = p >> 16;
    out_aw[p] = g_wpt[p] / __uint_as_float(g_maxw[b]);
}

// ---------------- launch ----------------
extern "C" void kernel_launch(void* const* d_in, const int* in_sizes, int n_in,
                              void* d_out, int out_size) {
    const float* x      = (const float*)d_in[0];
    const float* loc    = (const float*)d_in[1];
    const int*   idxa   = (const int*)  d_in[2];
    const float* aggw   = (const float*)d_in[3];
    const float* conv_w = (const float*)d_in[4];
    const float* conv_b = (const float*)d_in[5];
    const float* skip_w = (const float*)d_in[6];
    const float* gamma  = (const float*)d_in[7];
    const float* beta   = (const float*)d_in[8];
    const float* conf_w = (const float*)d_in[9];
    const float* conf_b = (const float*)d_in[10];

    float* out      = (float*)d_out;
    float* out_xd   = out;                                    // [4,4096,256]
    float* out_xout = out + (size_t)BB*NS*COUT;               // [4,16384,256]
    float* out_conf = out_xout + (size_t)BB*NN*COUT;          // [4,16384,1]
    float* out_aw   = out_conf + (size_t)BB*NN;               // [4,65536,1]
    float* out_idx  = out_aw   + (size_t)BB*NP;               // [4,65536]

    k_zero<<<2048, 256>>>();
    k_token2map<<<BB*NP/8, 256>>>(x, loc, idxa);
    k_transpose<<<CIN*COUT/256, 256>>>(skip_w);
    k_conv<<<dim3(WD/8, HD/8, BB*4), 256>>>(conv_w, conv_b);
    k_map2token<<<BB*NP/8, 256>>>(loc, idxa, aggw);
    k_skip<<<dim3(BB*NN/64, COUT/64), 256>>>(x);
    k_bnstats<<<BB*NN/256, 256>>>();
    k_bnfinal<<<1, 256>>>(gamma, beta);
    k_bnconf<<<BB*NN/8, 256>>>(conf_w, conf_b, out_xout, out_conf);
    k_cluster<<<BB*NP/8, 256>>>(loc, idxa, out_idx);
    k_xdown<<<BB*NS/8, 256>>>(out_xd);
    k_aggmax<<<BB*NP/256, 256>>>(loc, aggw);
    k_aggnorm<<<BB*NP/256, 256>>>(out_aw);
}